// round 1
// baseline (speedup 1.0000x reference)
#include <cuda_runtime.h>
#include <cstdint>

// Problem constants (fixed by the reference)
#define NP   65536
#define KC   1024
#define DIM  64

#define TM   64     // rows per block
#define TK   128    // codes per k-tile
#define ZSS  68     // zsT row stride (floats), mult of 4, !=0 mod 32 spread
#define WSS  132    // wsT row stride (floats)

// Output layout (concatenated reference tuple, float32)
#define OFF_ZQ    0
#define OFF_LOSS  4194304           // NP*DIM
#define OFF_IDX   4194305
#define OFF_CNT   4259841           // OFF_IDX + NP
#define OFF_AVG   4260865           // OFF_CNT + KC
#define OUT_FULL  4326401           // OFF_AVG + KC*DIM

// Scratch (device globals; no allocation allowed)
__device__ int   g_idx[NP];
__device__ int   g_cnt[KC];
__device__ float g_avg[KC * DIM];
__device__ float g_loss;

// ---------------------------------------------------------------------------
// Zero the accumulators used by the epilogue.
__global__ void zero_kernel() {
    int t = blockIdx.x * blockDim.x + threadIdx.x;
    if (t < KC * DIM) g_avg[t] = 0.0f;
    if (t < KC)       g_cnt[t] = 0;
    if (t == 0)       g_loss   = 0.0f;
}

// ---------------------------------------------------------------------------
// Argmin kernel: for each row n, find argmin_k ||z[n]-W[k]||^2 using the
// reference's exact fp32 formula dist = (s - 2*t) + w2 (rounded the same way)
// so the quantization of near-ties matches jnp.argmin.
__global__ void __launch_bounds__(256, 2)
argmin_kernel(const float* __restrict__ Z, const float* __restrict__ W) {
    extern __shared__ float smem[];
    float* zsT  = smem;                       // [DIM][ZSS]  (d-major, row minor)
    float* wsT  = smem + DIM * ZSS;           // [DIM][WSS]
    float* srow = smem + DIM * ZSS + DIM * WSS;       // [TM]
    float* w2s  = srow + TM;                  // [TK]

    const int tid = threadIdx.x;
    const int tx  = tid & 15;    // code-group selector (8 codes each)
    const int ty  = tid >> 4;    // row-group selector  (4 rows each)
    const int rowBase = blockIdx.x * TM;

    // Load Z tile, transposed. d strided by 16 per thread so the STS banks
    // spread (stride 68: tx*4 mod 32 pattern -> ~2-way only).
    #pragma unroll
    for (int i = 0; i < 4; i++) {
        int r = ty + i * 16;                       // 0..63
        #pragma unroll
        for (int j = 0; j < 4; j++) {
            int d = tx + j * 16;                   // 0..63
            zsT[d * ZSS + r] = Z[(size_t)(rowBase + r) * DIM + d];
        }
    }
    __syncthreads();

    // s = sum(z*z) per row, sequential d order, explicit round (no FMA).
    if (tid < TM) {
        float s = 0.0f;
        #pragma unroll
        for (int d = 0; d < DIM; d++) {
            float v = zsT[d * ZSS + tid];
            s = __fadd_rn(s, __fmul_rn(v, v));
        }
        srow[tid] = s;
    }

    float best[4];
    int   bidx[4];
    #pragma unroll
    for (int r = 0; r < 4; r++) { best[r] = 3.402823466e38f; bidx[r] = 0; }

    for (int kt = 0; kt < KC / TK; kt++) {
        __syncthreads();   // prev compute done; srow ready on first iter
        // Load W tile transposed
        #pragma unroll
        for (int i = 0; i < 8; i++) {
            int c = ty + i * 16;                   // 0..127
            #pragma unroll
            for (int j = 0; j < 4; j++) {
                int d = tx + j * 16;
                wsT[d * WSS + c] = W[(size_t)(kt * TK + c) * DIM + d];
            }
        }
        __syncthreads();
        // w2 = sum(w*w) per code, sequential, explicit round.
        if (tid < TK) {
            float s = 0.0f;
            #pragma unroll
            for (int d = 0; d < DIM; d++) {
                float v = wsT[d * WSS + tid];
                s = __fadd_rn(s, __fmul_rn(v, v));
            }
            w2s[tid] = s;
        }
        __syncthreads();

        // 4x8 register tile of dot products over d (FMA ok here: error << ulp(64))
        float acc[4][8];
        #pragma unroll
        for (int r = 0; r < 4; r++)
            #pragma unroll
            for (int c = 0; c < 8; c++) acc[r][c] = 0.0f;

        #pragma unroll 4
        for (int d = 0; d < DIM; d++) {
            float4 za = *reinterpret_cast<const float4*>(&zsT[d * ZSS + ty * 4]);
            float4 wa = *reinterpret_cast<const float4*>(&wsT[d * WSS + tx * 8]);
            float4 wb = *reinterpret_cast<const float4*>(&wsT[d * WSS + tx * 8 + 4]);
            float zr[4] = {za.x, za.y, za.z, za.w};
            float wr[8] = {wa.x, wa.y, wa.z, wa.w, wb.x, wb.y, wb.z, wb.w};
            #pragma unroll
            for (int r = 0; r < 4; r++)
                #pragma unroll
                for (int c = 0; c < 8; c++)
                    acc[r][c] = fmaf(zr[r], wr[c], acc[r][c]);
        }

        // dist = (s - 2t) + w2, exactly the reference's rounding sequence.
        #pragma unroll
        for (int r = 0; r < 4; r++) {
            float s = srow[ty * 4 + r];
            #pragma unroll
            for (int c = 0; c < 8; c++) {
                int   k    = kt * TK + tx * 8 + c;
                float a    = __fadd_rn(s, __fmul_rn(-2.0f, acc[r][c]));
                float dist = __fadd_rn(a, w2s[tx * 8 + c]);
                if (dist < best[r] || (dist == best[r] && k < bidx[r])) {
                    best[r] = dist; bidx[r] = k;
                }
            }
        }
    }

    // Reduce across the 16 tx lanes (half-warp butterfly), tie-break lowest k.
    #pragma unroll
    for (int r = 0; r < 4; r++) {
        float bd = best[r];
        int   bi = bidx[r];
        #pragma unroll
        for (int o = 1; o < 16; o <<= 1) {
            float od = __shfl_xor_sync(0xffffffffu, bd, o);
            int   oi = __shfl_xor_sync(0xffffffffu, bi, o);
            if (od < bd || (od == bd && oi < bi)) { bd = od; bi = oi; }
        }
        if (tx == 0) g_idx[rowBase + ty * 4 + r] = bi;
    }
}

// ---------------------------------------------------------------------------
// Epilogue: per element — STE output, commitment partial sum, EMA accumulators.
__global__ void epilogue_kernel(const float* __restrict__ Z,
                                const float* __restrict__ W,
                                float* __restrict__ out, int out_size) {
    const int tid = threadIdx.x;
    const int r   = blockIdx.x * 4 + (tid >> 6);
    const int d   = tid & 63;
    const int ci  = g_idx[r];

    float ze = Z[(size_t)r * DIM + d];
    float q  = W[(size_t)ci * DIM + d];

    // z_q_ste = z_e + (z_q - z_e), rounded exactly as the reference
    float st = __fadd_rn(ze, __fadd_rn(q, -ze));
    out[(size_t)r * DIM + d] = st;

    // commitment: (z_e - z_q)^2
    float diff = __fadd_rn(ze, -q);
    float sq   = __fmul_rn(diff, diff);

    __shared__ float red[256];
    red[tid] = sq;
    __syncthreads();
    #pragma unroll
    for (int o = 128; o > 0; o >>= 1) {
        if (tid < o) red[tid] += red[tid + o];
        __syncthreads();
    }
    if (tid == 0) atomicAdd(&g_loss, red[0]);

    atomicAdd(&g_avg[(size_t)ci * DIM + d], ze);
    if (d == 0) {
        atomicAdd(&g_cnt[ci], 1);
        if (out_size >= OFF_CNT) out[OFF_IDX + r] = (float)ci;
    }
}

// ---------------------------------------------------------------------------
// Finalize: loss scalar + EMA blends.
__global__ void finalize_kernel(const float* __restrict__ ema_count,
                                const float* __restrict__ ema_avg,
                                float* __restrict__ out, int out_size) {
    const int t = blockIdx.x * blockDim.x + threadIdx.x;
    const float DEC = 0.99f;
    const float OMD = (float)(1.0 - 0.99);   // matches python 1.0-DECAY -> f32

    if (t == 0 && out_size > OFF_LOSS) {
        // mean over NP*DIM (power of two -> exact scaling), * BETA=0.25 exact
        out[OFF_LOSS] = __fmul_rn(0.25f, __fmul_rn(g_loss, 1.0f / 4194304.0f));
    }
    if (t < KC && out_size >= OFF_CNT + KC) {
        out[OFF_CNT + t] = __fadd_rn(__fmul_rn(ema_count[t], DEC),
                                     __fmul_rn(OMD, (float)g_cnt[t]));
    }
    if (t < KC * DIM && out_size >= OUT_FULL) {
        out[OFF_AVG + t] = __fadd_rn(__fmul_rn(ema_avg[t], DEC),
                                     __fmul_rn(OMD, g_avg[t]));
    }
}

// ---------------------------------------------------------------------------
extern "C" void kernel_launch(void* const* d_in, const int* in_sizes, int n_in,
                              void* d_out, int out_size) {
    const float* Z         = (const float*)d_in[0];
    const float* W         = (const float*)d_in[1];
    const float* ema_count = (const float*)d_in[2];
    const float* ema_avg   = (const float*)d_in[3];
    float* out = (float*)d_out;

    const int SMEM_BYTES = (DIM * ZSS + DIM * WSS + TM + TK) * (int)sizeof(float);
    cudaFuncSetAttribute(argmin_kernel,
                         cudaFuncAttributeMaxDynamicSharedMemorySize, SMEM_BYTES);

    zero_kernel<<<(KC * DIM + 255) / 256, 256>>>();
    argmin_kernel<<<NP / TM, 256, SMEM_BYTES>>>(Z, W);
    epilogue_kernel<<<NP / 4, 256>>>(Z, W, out, out_size);
    finalize_kernel<<<(KC * DIM + 255) / 256, 256>>>(ema_count, ema_avg, out, out_size);
}